// round 11
// baseline (speedup 1.0000x reference)
#include <cuda_runtime.h>

// out[i] = x[i] - max(ceil(x[i]), 1.0f)
// Blackwell 256-bit streaming kernel: each thread does TWO front-batched
// 256-bit loads (ld.global.v8.f32) and two 256-bit stores. CTA owns one
// contiguous 16KB window. Perfect coalescing: each warp instruction touches
// 1024 contiguous bytes.

__device__ __forceinline__ float f(float v) {
    return v - fmaxf(ceilf(v), 1.0f);
}

struct V8 { float v[8]; };

__device__ __forceinline__ V8 ld256(const float* p) {
    V8 r;
    asm volatile("ld.global.v8.f32 {%0,%1,%2,%3,%4,%5,%6,%7}, [%8];"
        : "=f"(r.v[0]), "=f"(r.v[1]), "=f"(r.v[2]), "=f"(r.v[3]),
          "=f"(r.v[4]), "=f"(r.v[5]), "=f"(r.v[6]), "=f"(r.v[7])
        : "l"(p));
    return r;
}

__device__ __forceinline__ void st256(float* p, const V8& a) {
    asm volatile("st.global.v8.f32 [%0], {%1,%2,%3,%4,%5,%6,%7,%8};"
        :: "l"(p),
           "f"(a.v[0]), "f"(a.v[1]), "f"(a.v[2]), "f"(a.v[3]),
           "f"(a.v[4]), "f"(a.v[5]), "f"(a.v[6]), "f"(a.v[7])
        : "memory");
}

__device__ __forceinline__ V8 f8(V8 a) {
#pragma unroll
    for (int k = 0; k < 8; k++) a.v[k] = f(a.v[k]);
    return a;
}

// Each CTA: 256 threads * 2 slots * 8 floats = 4096 floats = 16KB window.
__global__ void __launch_bounds__(256)
recur_kernel_v8(const float* __restrict__ x, float* __restrict__ out) {
    unsigned base = blockIdx.x * 4096u + threadIdx.x * 8u;
    const float* p0 = x + base;
    const float* p1 = p0 + 2048u;
    // Front-batch both 256-bit loads before any store.
    V8 a = ld256(p0);
    V8 b = ld256(p1);
    st256(out + base, f8(a));
    st256(out + base + 2048u, f8(b));
}

__global__ void recur_kernel_tail(const float* __restrict__ x, float* __restrict__ out,
                                  long start, long n) {
    long i = start + (long)blockIdx.x * blockDim.x + threadIdx.x;
    if (i < n) out[i] = f(x[i]);
}

extern "C" void kernel_launch(void* const* d_in, const int* in_sizes, int n_in,
                              void* d_out, int out_size) {
    const float* x = (const float*)d_in[0];
    float* out = (float*)d_out;
    long n = (long)in_sizes[0];

    long nmain = (n / 4096) * 4096;   // full 16KB CTA windows
    if (nmain > 0) {
        unsigned blocks = (unsigned)(nmain / 4096);
        recur_kernel_v8<<<blocks, 256>>>(x, out);
    }
    long rem = n - nmain;
    if (rem > 0) {
        int threads = 256;
        int blocks = (int)((rem + threads - 1) / threads);
        recur_kernel_tail<<<blocks, threads>>>(x, out, nmain, n);
    }
}

// round 12
// speedup vs baseline: 1.0074x; 1.0074x over previous
#include <cuda_runtime.h>

// out[i] = x[i] - max(ceil(x[i]), 1.0f)
// Final streaming kernel: two front-batched float4 per thread, CTA-local
// contiguous 8KB window, zero guards in the main kernel (exact-window launch;
// any remainder handled by a scalar tail kernel).

__device__ __forceinline__ float f(float v) {
    return v - fmaxf(ceilf(v), 1.0f);
}

__device__ __forceinline__ float4 f4(float4 v) {
    float4 r;
    r.x = f(v.x); r.y = f(v.y); r.z = f(v.z); r.w = f(v.w);
    return r;
}

// Each CTA: 256 threads * 2 float4 = 512 float4 = 8KB contiguous window.
__global__ void __launch_bounds__(256)
recur_kernel_final(const float4* __restrict__ x, float4* __restrict__ out) {
    unsigned i0 = blockIdx.x * 512u + threadIdx.x;
    unsigned i1 = i0 + 256u;
    // Two independent 128-bit loads in flight before any store.
    float4 v0 = __ldcs(&x[i0]);
    float4 v1 = __ldcs(&x[i1]);
    __stcs(&out[i0], f4(v0));
    __stcs(&out[i1], f4(v1));
}

__global__ void recur_kernel_tail(const float* __restrict__ x, float* __restrict__ out,
                                  long start, long n) {
    long i = start + (long)blockIdx.x * blockDim.x + threadIdx.x;
    if (i < n) out[i] = f(x[i]);
}

extern "C" void kernel_launch(void* const* d_in, const int* in_sizes, int n_in,
                              void* d_out, int out_size) {
    const float* x = (const float*)d_in[0];
    float* out = (float*)d_out;
    long n = (long)in_sizes[0];

    // Main kernel covers exact 2048-float (8KB) CTA windows; tail covers the rest.
    long nmain = (n / 2048) * 2048;
    if (nmain > 0) {
        unsigned blocks = (unsigned)(nmain / 2048);
        recur_kernel_final<<<blocks, 256>>>((const float4*)x, (float4*)out);
    }
    long rem = n - nmain;
    if (rem > 0) {
        int threads = 256;
        int blocks = (int)((rem + threads - 1) / threads);
        recur_kernel_tail<<<blocks, threads>>>(x, out, nmain, n);
    }
}

// round 13
// speedup vs baseline: 1.0090x; 1.0016x over previous
#include <cuda_runtime.h>

// out[i] = x[i] - max(ceil(x[i]), 1.0f)
// Flat streaming kernel: two float4 per thread, front-batched, CTA-LOCAL
// layout: both accesses of a thread land in the same contiguous 8KB window
// owned by its CTA (better DRAM row-buffer locality than far-strided slots).
//
// Roofline-complete: 86.5% DRAM (6.86 TB/s) on irreducible 1:1 R/W traffic.
// MLP=2/thread is the measured knee; wider transactions, deeper MLP, guard
// removal, and grid-stride all measured neutral-or-worse.

__device__ __forceinline__ float f(float v) {
    return v - fmaxf(ceilf(v), 1.0f);
}

__device__ __forceinline__ float4 f4(float4 v) {
    float4 r;
    r.x = f(v.x); r.y = f(v.y); r.z = f(v.z); r.w = f(v.w);
    return r;
}

__global__ void __launch_bounds__(256)
recur_kernel_flat2b(const float4* __restrict__ x, float4* __restrict__ out, unsigned n4) {
    // Each CTA owns a contiguous window of 512 float4 (8KB).
    unsigned base = blockIdx.x * 512u;
    unsigned i0 = base + threadIdx.x;        // first 4KB half of window
    unsigned i1 = i0 + 256u;                 // second 4KB half of window

    if (i1 < n4) {
        // Fast path: both accesses in-bounds (always true for n = 2^27).
        float4 v0 = __ldcs(&x[i0]);
        float4 v1 = __ldcs(&x[i1]);
        __stcs(&out[i0], f4(v0));
        __stcs(&out[i1], f4(v1));
    } else {
        if (i0 < n4) __stcs(&out[i0], f4(__ldcs(&x[i0])));
    }
}

__global__ void recur_kernel_tail(const float* __restrict__ x, float* __restrict__ out,
                                  long start, long n) {
    long i = start + (long)blockIdx.x * blockDim.x + threadIdx.x;
    if (i < n) out[i] = f(x[i]);
}

extern "C" void kernel_launch(void* const* d_in, const int* in_sizes, int n_in,
                              void* d_out, int out_size) {
    const float* x = (const float*)d_in[0];
    float* out = (float*)d_out;
    long n = (long)in_sizes[0];

    long n4 = n / 4;
    if (n4 > 0) {
        unsigned un4 = (unsigned)n4;
        unsigned blocks = (un4 + 511u) / 512u;   // 512 float4 per CTA
        recur_kernel_flat2b<<<blocks, 256>>>((const float4*)x, (float4*)out, un4);
    }
    long rem_start = n4 * 4;
    long rem = n - rem_start;
    if (rem > 0) {
        int threads = 256;
        int blocks = (int)((rem + threads - 1) / threads);
        recur_kernel_tail<<<blocks, threads>>>(x, out, rem_start, n);
    }
}